// round 1
// baseline (speedup 1.0000x reference)
#include <cuda_runtime.h>
#include <math.h>

#define NN 50000
#define HD 128
#define EE 600000

// Scratch (device globals — no allocation allowed in kernel_launch)
__device__ float g_xw [NN * HD];
__device__ float g_agg[NN * HD];
__device__ float g_h1 [NN * HD];
__device__ float g_h2 [NN * HD];
__device__ float g_dinv[NN];
__device__ int   g_deg [NN];

__device__ __forceinline__ float elu(float v) {
    return v > 0.f ? v : expm1f(v);
}

// ---------------------------------------------------------------------------
// Degree / normalization
// ---------------------------------------------------------------------------
__global__ void k_zero_deg(int* __restrict__ deg) {
    int i = blockIdx.x * blockDim.x + threadIdx.x;
    if (i < NN) deg[i] = 0;
}

__global__ void k_hist(const int* __restrict__ dst, int* __restrict__ deg) {
    int i = blockIdx.x * blockDim.x + threadIdx.x;
    if (i < EE) atomicAdd(&deg[dst[i]], 1);
}

__global__ void k_dinv(const int* __restrict__ deg, float* __restrict__ dinv) {
    int i = blockIdx.x * blockDim.x + threadIdx.x;
    if (i < NN) dinv[i] = rsqrtf((float)deg[i] + 1.0f);
}

// ---------------------------------------------------------------------------
// GEMM: XW = X @ W  (M x 128 @ 128 x 128), epilogue also writes
// AGG = XW * dinv[row]^2 (the self-loop message), so AGG needs no memset.
// BM=128, BN=128, BK=32, 256 threads, 8x8 per thread, fp32.
// ---------------------------------------------------------------------------
__global__ __launch_bounds__(256) void k_gemm(
    const float* __restrict__ X, const float* __restrict__ W,
    const float* __restrict__ dinv,
    float* __restrict__ XW, float* __restrict__ AGG)
{
    __shared__ float As[32][132];   // A transposed: As[k][m], padded
    __shared__ float Bs[32][128];   // B natural:    Bs[k][n]

    const int tid = threadIdx.x;
    const int tx = tid & 15;        // output col group
    const int ty = tid >> 4;        // output row group
    const int blockRow = blockIdx.x * 128;

    float acc[8][8] = {};

    #pragma unroll
    for (int kt = 0; kt < 4; kt++) {
        const int k0 = kt * 32;

        // Load A tile (128 rows x 32 cols), transpose into As[k][m]
        #pragma unroll
        for (int i = 0; i < 4; i++) {
            int lin = tid + i * 256;          // 0..1023 float4 slots
            int r   = lin >> 3;               // row within tile (8 float4/row)
            int c4  = lin & 7;                // float4 index within 32 cols
            int grow = blockRow + r;
            float4 v = make_float4(0.f, 0.f, 0.f, 0.f);
            if (grow < NN) v = *(const float4*)(X + (size_t)grow * HD + k0 + c4 * 4);
            As[c4 * 4 + 0][r] = v.x;
            As[c4 * 4 + 1][r] = v.y;
            As[c4 * 4 + 2][r] = v.z;
            As[c4 * 4 + 3][r] = v.w;
        }
        // Load B tile (32 rows x 128 cols) directly
        #pragma unroll
        for (int i = 0; i < 4; i++) {
            int lin = tid + i * 256;
            int br  = lin >> 5;               // 32 float4 per 128-col row
            int bc  = lin & 31;
            *(float4*)(&Bs[br][bc * 4]) = *(const float4*)(W + (size_t)(k0 + br) * HD + bc * 4);
        }
        __syncthreads();

        #pragma unroll
        for (int k = 0; k < 32; k++) {
            float a[8], b[8];
            *(float4*)(a)     = *(const float4*)(&As[k][ty * 8]);
            *(float4*)(a + 4) = *(const float4*)(&As[k][ty * 8 + 4]);
            *(float4*)(b)     = *(const float4*)(&Bs[k][tx * 8]);
            *(float4*)(b + 4) = *(const float4*)(&Bs[k][tx * 8 + 4]);
            #pragma unroll
            for (int i = 0; i < 8; i++)
                #pragma unroll
                for (int j = 0; j < 8; j++)
                    acc[i][j] += a[i] * b[j];
        }
        __syncthreads();
    }

    #pragma unroll
    for (int i = 0; i < 8; i++) {
        int row = blockRow + ty * 8 + i;
        if (row >= NN) continue;
        float d = dinv[row];
        float d2 = d * d;
        #pragma unroll
        for (int j4 = 0; j4 < 2; j4++) {
            float4 v = make_float4(acc[i][j4 * 4 + 0], acc[i][j4 * 4 + 1],
                                   acc[i][j4 * 4 + 2], acc[i][j4 * 4 + 3]);
            *(float4*)(XW + (size_t)row * HD + tx * 8 + j4 * 4) = v;
            float4 w = make_float4(v.x * d2, v.y * d2, v.z * d2, v.w * d2);
            *(float4*)(AGG + (size_t)row * HD + tx * 8 + j4 * 4) = w;
        }
    }
}

// ---------------------------------------------------------------------------
// Edge scatter: AGG[dst] += XW[src] * (dinv[src]*dinv[dst]).
// One warp per edge; each lane handles a float4 (128 floats / 32 lanes).
// ---------------------------------------------------------------------------
__global__ __launch_bounds__(256) void k_scatter(
    const int* __restrict__ src, const int* __restrict__ dst,
    const float* __restrict__ dinv,
    const float* __restrict__ XW, float* __restrict__ AGG)
{
    int gtid = blockIdx.x * blockDim.x + threadIdx.x;
    int e    = gtid >> 5;
    int lane = gtid & 31;
    if (e >= EE) return;

    int s = src[e];
    int d = dst[e];
    float w = dinv[s] * dinv[d];

    float4 v = *(const float4*)(XW + (size_t)s * HD + lane * 4);
    float* out = AGG + (size_t)d * HD + lane * 4;
    atomicAdd(out + 0, v.x * w);
    atomicAdd(out + 1, v.y * w);
    atomicAdd(out + 2, v.z * w);
    atomicAdd(out + 3, v.w * w);
}

// ---------------------------------------------------------------------------
// Finalize: H = elu(AGG + b)   (vectorized, float4 per thread)
// ---------------------------------------------------------------------------
__global__ void k_finalize(const float* __restrict__ AGG,
                           const float* __restrict__ b,
                           float* __restrict__ Hout)
{
    int i = blockIdx.x * blockDim.x + threadIdx.x;   // over NN*32 float4s
    if (i >= NN * (HD / 4)) return;
    int c4 = (i & 31) * 4;
    float4 a  = *(const float4*)(AGG + (size_t)i * 4);
    float4 bb = *(const float4*)(b + c4);
    float4 r;
    r.x = elu(a.x + bb.x);
    r.y = elu(a.y + bb.y);
    r.z = elu(a.z + bb.z);
    r.w = elu(a.w + bb.w);
    *(float4*)(Hout + (size_t)i * 4) = r;
}

// ---------------------------------------------------------------------------
// Output head: S = elu(h @ Wm2 + bm2)   (N x 10 from 128-dim). Warp per row.
// (Wm1/bm1 are dead code in the reference: only the last loop iter survives.)
// ---------------------------------------------------------------------------
__global__ __launch_bounds__(256) void k_mlp(
    const float* __restrict__ Hin, const float* __restrict__ Wm,
    const float* __restrict__ bm, float* __restrict__ S)
{
    __shared__ float Ws[HD * 10];
    __shared__ float bs[10];
    int tid = threadIdx.x;
    for (int i = tid; i < HD * 10; i += 256) Ws[i] = Wm[i];
    if (tid < 10) bs[tid] = bm[tid];
    __syncthreads();

    int warp = tid >> 5, lane = tid & 31;
    int row = blockIdx.x * 8 + warp;
    if (row >= NN) return;

    float acc[10] = {};
    #pragma unroll
    for (int kk = 0; kk < 4; kk++) {
        int k = kk * 32 + lane;
        float hv = Hin[(size_t)row * HD + k];
        #pragma unroll
        for (int c = 0; c < 10; c++) acc[c] += hv * Ws[k * 10 + c];
    }
    #pragma unroll
    for (int c = 0; c < 10; c++) {
        #pragma unroll
        for (int off = 16; off; off >>= 1)
            acc[c] += __shfl_down_sync(0xffffffffu, acc[c], off);
    }
    if (lane == 0) {
        #pragma unroll
        for (int c = 0; c < 10; c++) {
            float v = acc[c] + bs[c];
            S[(size_t)row * 10 + c] = elu(v);
        }
    }
}

// ---------------------------------------------------------------------------
extern "C" void kernel_launch(void* const* d_in, const int* in_sizes, int n_in,
                              void* d_out, int out_size)
{
    const float* x   = (const float*)d_in[0];
    const int*   ei  = (const int*)d_in[1];
    const int*   src = ei;
    const int*   dst = ei + EE;
    const float* W[4] = {(const float*)d_in[2], (const float*)d_in[4],
                         (const float*)d_in[6], (const float*)d_in[8]};
    const float* b[4] = {(const float*)d_in[3], (const float*)d_in[5],
                         (const float*)d_in[7], (const float*)d_in[9]};
    const float* Wm2 = (const float*)d_in[12];
    const float* bm2 = (const float*)d_in[13];

    float* out_h = (float*)d_out;                 // [NN, 128]
    float* out_S = out_h + (size_t)NN * HD;       // [NN, 10]

    float *xw, *agg, *h1, *h2, *dinv;
    int* deg;
    cudaGetSymbolAddress((void**)&xw,   g_xw);
    cudaGetSymbolAddress((void**)&agg,  g_agg);
    cudaGetSymbolAddress((void**)&h1,   g_h1);
    cudaGetSymbolAddress((void**)&h2,   g_h2);
    cudaGetSymbolAddress((void**)&dinv, g_dinv);
    cudaGetSymbolAddress((void**)&deg,  g_deg);

    // degree + normalization (same for all 4 layers)
    k_zero_deg<<<(NN + 255) / 256, 256>>>(deg);
    k_hist<<<(EE + 255) / 256, 256>>>(dst, deg);
    k_dinv<<<(NN + 255) / 256, 256>>>(deg, dinv);

    const int gemm_blocks    = (NN + 127) / 128;          // 391
    const int scatter_blocks = (EE * 32 + 255) / 256;     // 75000
    const int fin_blocks     = (NN * (HD / 4) + 255) / 256;

    const float* in = x;
    float* houts[4] = {h1, h2, h1, out_h};
    for (int l = 0; l < 4; l++) {
        k_gemm<<<gemm_blocks, 256>>>(in, W[l], dinv, xw, agg);
        k_scatter<<<scatter_blocks, 256>>>(src, dst, dinv, xw, agg);
        k_finalize<<<fin_blocks, 256>>>(agg, b[l], houts[l]);
        in = houts[l];
    }

    k_mlp<<<(NN + 7) / 8, 256>>>(out_h, Wm2, bm2, out_S);
}

// round 3
// speedup vs baseline: 3.0133x; 3.0133x over previous
#include <cuda_runtime.h>
#include <math.h>

#define NN 50000
#define HD 128
#define EE 600000
#define BK 16

// Scratch (device globals — no allocation allowed in kernel_launch)
__device__ float g_xw [NN * HD];
__device__ float g_h1 [NN * HD];
__device__ float g_h2 [NN * HD];
__device__ float g_dinv[NN];
__device__ int   g_deg [NN];
__device__ int   g_rowptr[NN + 1];
__device__ int   g_head[NN];
__device__ unsigned long long g_csr[EE];   // [w:f32 | src:i32]

__device__ __forceinline__ float elu(float v) {
    return v > 0.f ? v : expm1f(v);
}

// packed f32x2 FMA (Blackwell): d = a*b + d, elementwise on the pair
__device__ __forceinline__ void ffma2(unsigned long long& d,
                                      unsigned long long a,
                                      unsigned long long b) {
    asm("fma.rn.f32x2 %0, %1, %2, %0;" : "+l"(d) : "l"(a), "l"(b));
}

union F4U { float4 v; unsigned long long u[2]; };
union U2  { unsigned long long u; float2 f; };

// ---------------------------------------------------------------------------
// Degree / normalization / CSR build
// ---------------------------------------------------------------------------
__global__ void k_zero_deg(int* __restrict__ deg) {
    int i = blockIdx.x * blockDim.x + threadIdx.x;
    if (i < NN) deg[i] = 0;
}

__global__ void k_hist(const int* __restrict__ dst, int* __restrict__ deg) {
    int i = blockIdx.x * blockDim.x + threadIdx.x;
    if (i < EE) atomicAdd(&deg[dst[i]], 1);
}

__global__ void k_dinv(const int* __restrict__ deg, float* __restrict__ dinv) {
    int i = blockIdx.x * blockDim.x + threadIdx.x;
    if (i < NN) dinv[i] = rsqrtf((float)deg[i] + 1.0f);
}

// Single-block exclusive prefix sum over deg -> rowptr, head
__global__ void k_scan(const int* __restrict__ deg) {
    __shared__ int warpsum[32];
    __shared__ int carry_s;
    int tid = threadIdx.x;
    int lane = tid & 31, wid = tid >> 5;
    if (tid == 0) carry_s = 0;
    __syncthreads();

    for (int base = 0; base < NN; base += 1024) {
        int i = base + tid;
        int v = (i < NN) ? deg[i] : 0;
        // inclusive warp scan
        int x = v;
        #pragma unroll
        for (int off = 1; off < 32; off <<= 1) {
            int y = __shfl_up_sync(0xffffffffu, x, off);
            if (lane >= off) x += y;
        }
        if (lane == 31) warpsum[wid] = x;
        __syncthreads();
        if (wid == 0) {
            int s = warpsum[lane];
            #pragma unroll
            for (int off = 1; off < 32; off <<= 1) {
                int y = __shfl_up_sync(0xffffffffu, s, off);
                if (lane >= off) s += y;
            }
            warpsum[lane] = s;
        }
        __syncthreads();
        int excl = x - v + (wid ? warpsum[wid - 1] : 0) + carry_s;
        if (i < NN) { g_rowptr[i] = excl; g_head[i] = excl; }
        __syncthreads();
        if (tid == 0) carry_s += warpsum[31];
        __syncthreads();
    }
    if (tid == 0) g_rowptr[NN] = carry_s;   // == EE
}

__global__ void k_fill(const int* __restrict__ src, const int* __restrict__ dst,
                       const float* __restrict__ dinv) {
    int e = blockIdx.x * blockDim.x + threadIdx.x;
    if (e >= EE) return;
    int s = src[e];
    int d = dst[e];
    float w = dinv[s] * dinv[d];
    int pos = atomicAdd(&g_head[d], 1);
    g_csr[pos] = ((unsigned long long)__float_as_uint(w) << 32) | (unsigned)s;
}

// ---------------------------------------------------------------------------
// GEMM: XW = X @ W (N x 128 @ 128 x 128) with packed f32x2 FMAs.
// A tile stored DUPLICATED in smem: Asd[k][2m]=Asd[k][2m+1]=A[m][k], so an
// LDS.128 yields two ready (a,a) pairs; B pairs are natural adjacency.
// 256 threads, 8x8 per thread (as 8x4 f32x2 pairs).
// ---------------------------------------------------------------------------
__global__ __launch_bounds__(256, 2) void k_gemm(
    const float* __restrict__ X, const float* __restrict__ W,
    float* __restrict__ XW)
{
    __shared__ float Asd[BK][260];   // duplicated A, padded
    __shared__ float Bs [BK][128];

    const int tid = threadIdx.x;
    const int tx = tid & 15;        // output col group (8 cols)
    const int ty = tid >> 4;        // output row group (8 rows)
    const int blockRow = blockIdx.x * 128;

    unsigned long long acc2[8][4] = {};

    #pragma unroll
    for (int kt = 0; kt < HD / BK; kt++) {
        const int k0 = kt * BK;

        // Load A tile (128 rows x 16 cols), store transposed + duplicated
        #pragma unroll
        for (int i = 0; i < 2; i++) {
            int lin = tid + i * 256;          // 0..511 float4 slots
            int r   = lin >> 2;               // row (4 float4/row)
            int c4  = lin & 3;
            int grow = blockRow + r;
            float4 v = make_float4(0.f, 0.f, 0.f, 0.f);
            if (grow < NN) v = *(const float4*)(X + (size_t)grow * HD + k0 + c4 * 4);
            *(float2*)(&Asd[c4 * 4 + 0][2 * r]) = make_float2(v.x, v.x);
            *(float2*)(&Asd[c4 * 4 + 1][2 * r]) = make_float2(v.y, v.y);
            *(float2*)(&Asd[c4 * 4 + 2][2 * r]) = make_float2(v.z, v.z);
            *(float2*)(&Asd[c4 * 4 + 3][2 * r]) = make_float2(v.w, v.w);
        }
        // Load B tile (16 rows x 128 cols)
        #pragma unroll
        for (int i = 0; i < 2; i++) {
            int lin = tid + i * 256;
            int br  = lin >> 5;
            int bc  = lin & 31;
            *(float4*)(&Bs[br][bc * 4]) = *(const float4*)(W + (size_t)(k0 + br) * HD + bc * 4);
        }
        __syncthreads();

        #pragma unroll
        for (int k = 0; k < BK; k++) {
            F4U a0, a1, a2, a3, b0, b1;
            a0.v = *(const float4*)(&Asd[k][ty * 16 + 0]);
            a1.v = *(const float4*)(&Asd[k][ty * 16 + 4]);
            a2.v = *(const float4*)(&Asd[k][ty * 16 + 8]);
            a3.v = *(const float4*)(&Asd[k][ty * 16 + 12]);
            b0.v = *(const float4*)(&Bs[k][tx * 8]);
            b1.v = *(const float4*)(&Bs[k][tx * 8 + 4]);
            unsigned long long Ad[8] = {a0.u[0], a0.u[1], a1.u[0], a1.u[1],
                                        a2.u[0], a2.u[1], a3.u[0], a3.u[1]};
            unsigned long long Bp[4] = {b0.u[0], b0.u[1], b1.u[0], b1.u[1]};
            #pragma unroll
            for (int i = 0; i < 8; i++)
                #pragma unroll
                for (int j2 = 0; j2 < 4; j2++)
                    ffma2(acc2[i][j2], Ad[i], Bp[j2]);
        }
        __syncthreads();
    }

    #pragma unroll
    for (int i = 0; i < 8; i++) {
        int row = blockRow + ty * 8 + i;
        if (row >= NN) continue;
        U2 u0, u1, u2, u3;
        u0.u = acc2[i][0]; u1.u = acc2[i][1];
        u2.u = acc2[i][2]; u3.u = acc2[i][3];
        float4 o0 = make_float4(u0.f.x, u0.f.y, u1.f.x, u1.f.y);
        float4 o1 = make_float4(u2.f.x, u2.f.y, u3.f.x, u3.f.y);
        *(float4*)(XW + (size_t)row * HD + tx * 8)     = o0;
        *(float4*)(XW + (size_t)row * HD + tx * 8 + 4) = o1;
    }
}

// ---------------------------------------------------------------------------
// CSR gather + self-loop + bias + ELU fused. One warp per dst node;
// lane owns a float4 (128 cols / 32 lanes). No atomics.
// ---------------------------------------------------------------------------
__global__ __launch_bounds__(256) void k_gather(
    const float* __restrict__ XW, const float* __restrict__ dinv,
    const float* __restrict__ bias, float* __restrict__ H)
{
    int gt   = blockIdx.x * blockDim.x + threadIdx.x;
    int node = gt >> 5;
    int lane = gt & 31;
    if (node >= NN) return;

    int beg = g_rowptr[node];
    int end = g_rowptr[node + 1];
    float d  = dinv[node];
    float d2 = d * d;

    float4 acc = *(const float4*)(XW + (size_t)node * HD + lane * 4);
    acc.x *= d2; acc.y *= d2; acc.z *= d2; acc.w *= d2;

    for (int j = beg; j < end; j++) {
        unsigned long long pv = g_csr[j];           // broadcast within warp
        int   s = (int)(unsigned)(pv & 0xffffffffu);
        float w = __uint_as_float((unsigned)(pv >> 32));
        float4 v = *(const float4*)(XW + (size_t)s * HD + lane * 4);
        acc.x = fmaf(w, v.x, acc.x);
        acc.y = fmaf(w, v.y, acc.y);
        acc.z = fmaf(w, v.z, acc.z);
        acc.w = fmaf(w, v.w, acc.w);
    }

    float4 bb = *(const float4*)(bias + lane * 4);
    float4 r;
    r.x = elu(acc.x + bb.x);
    r.y = elu(acc.y + bb.y);
    r.z = elu(acc.z + bb.z);
    r.w = elu(acc.w + bb.w);
    *(float4*)(H + (size_t)node * HD + lane * 4) = r;
}

// ---------------------------------------------------------------------------
// Output head: S = elu(h @ Wm2 + bm2) (N x 10). Warp per row.
// (Wm1/bm1 are dead code in the reference.)
// ---------------------------------------------------------------------------
__global__ __launch_bounds__(256) void k_mlp(
    const float* __restrict__ Hin, const float* __restrict__ Wm,
    const float* __restrict__ bm, float* __restrict__ S)
{
    __shared__ float Ws[HD * 10];
    __shared__ float bs[10];
    int tid = threadIdx.x;
    for (int i = tid; i < HD * 10; i += 256) Ws[i] = Wm[i];
    if (tid < 10) bs[tid] = bm[tid];
    __syncthreads();

    int warp = tid >> 5, lane = tid & 31;
    int row = blockIdx.x * 8 + warp;
    if (row >= NN) return;

    float acc[10] = {};
    #pragma unroll
    for (int kk = 0; kk < 4; kk++) {
        int k = kk * 32 + lane;
        float hv = Hin[(size_t)row * HD + k];
        #pragma unroll
        for (int c = 0; c < 10; c++) acc[c] += hv * Ws[k * 10 + c];
    }
    #pragma unroll
    for (int c = 0; c < 10; c++) {
        #pragma unroll
        for (int off = 16; off; off >>= 1)
            acc[c] += __shfl_down_sync(0xffffffffu, acc[c], off);
    }
    if (lane == 0) {
        #pragma unroll
        for (int c = 0; c < 10; c++) {
            float v = acc[c] + bs[c];
            S[(size_t)row * 10 + c] = elu(v);
        }
    }
}

// ---------------------------------------------------------------------------
extern "C" void kernel_launch(void* const* d_in, const int* in_sizes, int n_in,
                              void* d_out, int out_size)
{
    const float* x   = (const float*)d_in[0];
    const int*   ei  = (const int*)d_in[1];
    const int*   src = ei;
    const int*   dst = ei + EE;
    const float* W[4] = {(const float*)d_in[2], (const float*)d_in[4],
                         (const float*)d_in[6], (const float*)d_in[8]};
    const float* b[4] = {(const float*)d_in[3], (const float*)d_in[5],
                         (const float*)d_in[7], (const float*)d_in[9]};
    const float* Wm2 = (const float*)d_in[12];
    const float* bm2 = (const float*)d_in[13];

    float* out_h = (float*)d_out;                 // [NN, 128]
    float* out_S = out_h + (size_t)NN * HD;       // [NN, 10]

    float *xw, *h1, *h2, *dinv;
    int* deg;
    cudaGetSymbolAddress((void**)&xw,   g_xw);
    cudaGetSymbolAddress((void**)&h1,   g_h1);
    cudaGetSymbolAddress((void**)&h2,   g_h2);
    cudaGetSymbolAddress((void**)&dinv, g_dinv);
    cudaGetSymbolAddress((void**)&deg,  g_deg);

    // Degree, normalization, CSR build (once per launch)
    k_zero_deg<<<(NN + 255) / 256, 256>>>(deg);
    k_hist<<<(EE + 255) / 256, 256>>>(dst, deg);
    k_dinv<<<(NN + 255) / 256, 256>>>(deg, dinv);
    k_scan<<<1, 1024>>>(deg);
    k_fill<<<(EE + 255) / 256, 256>>>(src, dst, dinv);

    const int gemm_blocks   = (NN + 127) / 128;           // 391
    const int gather_blocks = (NN * 32 + 255) / 256;      // 6250

    const float* in = x;
    float* houts[4] = {h1, h2, h1, out_h};
    for (int l = 0; l < 4; l++) {
        k_gemm<<<gemm_blocks, 256>>>(in, W[l], xw);
        k_gather<<<gather_blocks, 256>>>(xw, dinv, b[l], houts[l]);
        in = houts[l];
    }

    k_mlp<<<(NN + 7) / 8, 256>>>(out_h, Wm2, bm2, out_S);
}

// round 4
// speedup vs baseline: 3.1944x; 1.0601x over previous
#include <cuda_runtime.h>
#include <math.h>

#define NN 50000
#define HD 128
#define EE 600000
#define BK 16
#define SCAN_BLOCKS ((NN + 255) / 256)   // 196

// Scratch (device globals — no allocation allowed in kernel_launch)
__device__ float g_xw [NN * HD];
__device__ float g_h1 [NN * HD];
__device__ float g_h2 [NN * HD];
__device__ float g_dinv[NN];
__device__ int   g_deg [NN];
__device__ int   g_rowptr[NN + 1];
__device__ int   g_head[NN];
__device__ int   g_bsum[SCAN_BLOCKS];
__device__ int   g_boff[SCAN_BLOCKS];
__device__ unsigned long long g_csr[EE];   // [w:f32 | src:i32]

__device__ __forceinline__ float elu(float v) {
    return v > 0.f ? v : expm1f(v);
}

// packed f32x2 FMA (Blackwell): d = a*b + d, elementwise on the pair
__device__ __forceinline__ void ffma2(unsigned long long& d,
                                      unsigned long long a,
                                      unsigned long long b) {
    asm("fma.rn.f32x2 %0, %1, %2, %0;" : "+l"(d) : "l"(a), "l"(b));
}

union F4U { float4 v; unsigned long long u[2]; };
union U2  { unsigned long long u; float2 f; };

// ---------------------------------------------------------------------------
// Degree / normalization / CSR build
// ---------------------------------------------------------------------------
__global__ void k_zero_deg(int* __restrict__ deg) {
    int i = blockIdx.x * blockDim.x + threadIdx.x;
    if (i < NN) deg[i] = 0;
}

__global__ void k_hist(const int* __restrict__ dst, int* __restrict__ deg) {
    int i = blockIdx.x * blockDim.x + threadIdx.x;
    if (i < EE) atomicAdd(&deg[dst[i]], 1);
}

// Phase 1: per-block reduction of deg (also computes dinv, fused)
__global__ void k_blockred(const int* __restrict__ deg, float* __restrict__ dinv) {
    __shared__ int wsum[8];
    int tid = threadIdx.x;
    int i = blockIdx.x * 256 + tid;
    int v = (i < NN) ? deg[i] : 0;
    if (i < NN) dinv[i] = rsqrtf((float)v + 1.0f);

    int x = v;
    #pragma unroll
    for (int off = 16; off; off >>= 1)
        x += __shfl_down_sync(0xffffffffu, x, off);
    if ((tid & 31) == 0) wsum[tid >> 5] = x;
    __syncthreads();
    if (tid < 8) {
        int s = wsum[tid];
        #pragma unroll
        for (int off = 4; off; off >>= 1)
            s += __shfl_down_sync(0xffu, s, off);
        if (tid == 0) g_bsum[blockIdx.x] = s;
    }
}

// Phase 2: single small block scans the block sums (exclusive)
__global__ void k_scansums() {
    __shared__ int wsum[8];
    int tid = threadIdx.x;     // 256 threads cover SCAN_BLOCKS=196
    int lane = tid & 31, wid = tid >> 5;
    int v = (tid < SCAN_BLOCKS) ? g_bsum[tid] : 0;
    int x = v;
    #pragma unroll
    for (int off = 1; off < 32; off <<= 1) {
        int y = __shfl_up_sync(0xffffffffu, x, off);
        if (lane >= off) x += y;
    }
    if (lane == 31) wsum[wid] = x;
    __syncthreads();
    if (wid == 0 && lane < 8) {
        int s = wsum[lane];
        #pragma unroll
        for (int off = 1; off < 8; off <<= 1) {
            int y = __shfl_up_sync(0xffu, s, off);
            if (lane >= off) s += y;
        }
        wsum[lane] = s;
    }
    __syncthreads();
    int excl = x - v + (wid ? wsum[wid - 1] : 0);
    if (tid < SCAN_BLOCKS) g_boff[tid] = excl;
    if (tid == SCAN_BLOCKS - 1) g_rowptr[NN] = excl + v;   // total == EE
}

// Phase 3: per-block rescan + add block offset -> rowptr, head
__global__ void k_scanfinal(const int* __restrict__ deg) {
    __shared__ int wsum[8];
    int tid = threadIdx.x;
    int lane = tid & 31, wid = tid >> 5;
    int i = blockIdx.x * 256 + tid;
    int v = (i < NN) ? deg[i] : 0;
    int x = v;
    #pragma unroll
    for (int off = 1; off < 32; off <<= 1) {
        int y = __shfl_up_sync(0xffffffffu, x, off);
        if (lane >= off) x += y;
    }
    if (lane == 31) wsum[wid] = x;
    __syncthreads();
    if (wid == 0 && lane < 8) {
        int s = wsum[lane];
        #pragma unroll
        for (int off = 1; off < 8; off <<= 1) {
            int y = __shfl_up_sync(0xffu, s, off);
            if (lane >= off) s += y;
        }
        wsum[lane] = s;
    }
    __syncthreads();
    int excl = x - v + (wid ? wsum[wid - 1] : 0) + g_boff[blockIdx.x];
    if (i < NN) { g_rowptr[i] = excl; g_head[i] = excl; }
}

__global__ void k_fill(const int* __restrict__ src, const int* __restrict__ dst,
                       const float* __restrict__ dinv) {
    int e = blockIdx.x * blockDim.x + threadIdx.x;
    if (e >= EE) return;
    int s = src[e];
    int d = dst[e];
    float w = dinv[s] * dinv[d];
    int pos = atomicAdd(&g_head[d], 1);
    g_csr[pos] = ((unsigned long long)__float_as_uint(w) << 32) | (unsigned)s;
}

// ---------------------------------------------------------------------------
// GEMM: XW = X @ W (N x 128 @ 128 x 128) with packed f32x2 FMAs and
// register double-buffering of the global loads.
// A tile stored DUPLICATED in smem: Asd[k][2m]=Asd[k][2m+1]=A[m][k], so an
// LDS.128 yields two ready (a,a) pairs; B pairs are natural adjacency.
// 256 threads, 8x8 per thread (as 8x4 f32x2 pairs).
// ---------------------------------------------------------------------------
__global__ __launch_bounds__(256, 2) void k_gemm(
    const float* __restrict__ X, const float* __restrict__ W,
    float* __restrict__ XW)
{
    __shared__ float Asd[BK][260];   // duplicated A, padded
    __shared__ float Bs [BK][128];

    const int tid = threadIdx.x;
    const int tx = tid & 15;        // output col group (8 cols)
    const int ty = tid >> 4;        // output row group (8 rows)
    const int blockRow = blockIdx.x * 128;

    // A-load geometry (2 float4 per thread per tile)
    int ar[2], ac4[2];  bool aok[2];
    int br_[2], bc_[2];
    #pragma unroll
    for (int i = 0; i < 2; i++) {
        int lin = tid + i * 256;
        ar[i]  = lin >> 2;
        ac4[i] = lin & 3;
        aok[i] = (blockRow + ar[i]) < NN;
        br_[i] = lin >> 5;
        bc_[i] = lin & 31;
    }

    unsigned long long acc2[8][4] = {};

    // Prologue: fetch tile 0 into registers
    float4 avr[2], bvr[2];
    #pragma unroll
    for (int i = 0; i < 2; i++) {
        avr[i] = make_float4(0.f, 0.f, 0.f, 0.f);
        if (aok[i]) avr[i] = *(const float4*)(X + (size_t)(blockRow + ar[i]) * HD + ac4[i] * 4);
        bvr[i] = *(const float4*)(W + (size_t)br_[i] * HD + bc_[i] * 4);
    }

    #pragma unroll
    for (int kt = 0; kt < HD / BK; kt++) {
        // Store prefetched tile into smem
        #pragma unroll
        for (int i = 0; i < 2; i++) {
            float4 v = avr[i];
            *(float2*)(&Asd[ac4[i] * 4 + 0][2 * ar[i]]) = make_float2(v.x, v.x);
            *(float2*)(&Asd[ac4[i] * 4 + 1][2 * ar[i]]) = make_float2(v.y, v.y);
            *(float2*)(&Asd[ac4[i] * 4 + 2][2 * ar[i]]) = make_float2(v.z, v.z);
            *(float2*)(&Asd[ac4[i] * 4 + 3][2 * ar[i]]) = make_float2(v.w, v.w);
            *(float4*)(&Bs[br_[i]][bc_[i] * 4]) = bvr[i];
        }
        __syncthreads();

        // Prefetch next tile (LDGs overlap with the FMA block below)
        if (kt + 1 < HD / BK) {
            const int k0n = (kt + 1) * BK;
            #pragma unroll
            for (int i = 0; i < 2; i++) {
                avr[i] = make_float4(0.f, 0.f, 0.f, 0.f);
                if (aok[i]) avr[i] = *(const float4*)(X + (size_t)(blockRow + ar[i]) * HD + k0n + ac4[i] * 4);
                bvr[i] = *(const float4*)(W + (size_t)(k0n + br_[i]) * HD + bc_[i] * 4);
            }
        }

        #pragma unroll
        for (int k = 0; k < BK; k++) {
            F4U a0, a1, a2, a3, b0, b1;
            a0.v = *(const float4*)(&Asd[k][ty * 16 + 0]);
            a1.v = *(const float4*)(&Asd[k][ty * 16 + 4]);
            a2.v = *(const float4*)(&Asd[k][ty * 16 + 8]);
            a3.v = *(const float4*)(&Asd[k][ty * 16 + 12]);
            b0.v = *(const float4*)(&Bs[k][tx * 8]);
            b1.v = *(const float4*)(&Bs[k][tx * 8 + 4]);
            unsigned long long Ad[8] = {a0.u[0], a0.u[1], a1.u[0], a1.u[1],
                                        a2.u[0], a2.u[1], a3.u[0], a3.u[1]};
            unsigned long long Bp[4] = {b0.u[0], b0.u[1], b1.u[0], b1.u[1]};
            #pragma unroll
            for (int i = 0; i < 8; i++)
                #pragma unroll
                for (int j2 = 0; j2 < 4; j2++)
                    ffma2(acc2[i][j2], Ad[i], Bp[j2]);
        }
        __syncthreads();
    }

    #pragma unroll
    for (int i = 0; i < 8; i++) {
        int row = blockRow + ty * 8 + i;
        if (row >= NN) continue;
        U2 u0, u1, u2, u3;
        u0.u = acc2[i][0]; u1.u = acc2[i][1];
        u2.u = acc2[i][2]; u3.u = acc2[i][3];
        float4 o0 = make_float4(u0.f.x, u0.f.y, u1.f.x, u1.f.y);
        float4 o1 = make_float4(u2.f.x, u2.f.y, u3.f.x, u3.f.y);
        *(float4*)(XW + (size_t)row * HD + tx * 8)     = o0;
        *(float4*)(XW + (size_t)row * HD + tx * 8 + 4) = o1;
    }
}

// ---------------------------------------------------------------------------
// CSR gather + self-loop + bias + ELU fused. One warp per dst node;
// lane owns a float4 (128 cols / 32 lanes). No atomics.
// ---------------------------------------------------------------------------
__global__ __launch_bounds__(256) void k_gather(
    const float* __restrict__ XW, const float* __restrict__ dinv,
    const float* __restrict__ bias, float* __restrict__ H)
{
    int gt   = blockIdx.x * blockDim.x + threadIdx.x;
    int node = gt >> 5;
    int lane = gt & 31;
    if (node >= NN) return;

    int beg = g_rowptr[node];
    int end = g_rowptr[node + 1];
    float d  = dinv[node];
    float d2 = d * d;

    float4 acc = *(const float4*)(XW + (size_t)node * HD + lane * 4);
    acc.x *= d2; acc.y *= d2; acc.z *= d2; acc.w *= d2;

    for (int j = beg; j < end; j++) {
        unsigned long long pv = g_csr[j];           // broadcast within warp
        int   s = (int)(unsigned)(pv & 0xffffffffu);
        float w = __uint_as_float((unsigned)(pv >> 32));
        float4 v = *(const float4*)(XW + (size_t)s * HD + lane * 4);
        acc.x = fmaf(w, v.x, acc.x);
        acc.y = fmaf(w, v.y, acc.y);
        acc.z = fmaf(w, v.z, acc.z);
        acc.w = fmaf(w, v.w, acc.w);
    }

    float4 bb = *(const float4*)(bias + lane * 4);
    float4 r;
    r.x = elu(acc.x + bb.x);
    r.y = elu(acc.y + bb.y);
    r.z = elu(acc.z + bb.z);
    r.w = elu(acc.w + bb.w);
    *(float4*)(H + (size_t)node * HD + lane * 4) = r;
}

// ---------------------------------------------------------------------------
// Output head: S = elu(h @ Wm2 + bm2) (N x 10). Warp per row.
// (Wm1/bm1 are dead code in the reference.)
// ---------------------------------------------------------------------------
__global__ __launch_bounds__(256) void k_mlp(
    const float* __restrict__ Hin, const float* __restrict__ Wm,
    const float* __restrict__ bm, float* __restrict__ S)
{
    __shared__ float Ws[HD * 10];
    __shared__ float bs[10];
    int tid = threadIdx.x;
    for (int i = tid; i < HD * 10; i += 256) Ws[i] = Wm[i];
    if (tid < 10) bs[tid] = bm[tid];
    __syncthreads();

    int warp = tid >> 5, lane = tid & 31;
    int row = blockIdx.x * 8 + warp;
    if (row >= NN) return;

    float acc[10] = {};
    #pragma unroll
    for (int kk = 0; kk < 4; kk++) {
        int k = kk * 32 + lane;
        float hv = Hin[(size_t)row * HD + k];
        #pragma unroll
        for (int c = 0; c < 10; c++) acc[c] += hv * Ws[k * 10 + c];
    }
    #pragma unroll
    for (int c = 0; c < 10; c++) {
        #pragma unroll
        for (int off = 16; off; off >>= 1)
            acc[c] += __shfl_down_sync(0xffffffffu, acc[c], off);
    }
    if (lane == 0) {
        #pragma unroll
        for (int c = 0; c < 10; c++) {
            float v = acc[c] + bs[c];
            S[(size_t)row * 10 + c] = elu(v);
        }
    }
}

// ---------------------------------------------------------------------------
extern "C" void kernel_launch(void* const* d_in, const int* in_sizes, int n_in,
                              void* d_out, int out_size)
{
    const float* x   = (const float*)d_in[0];
    const int*   ei  = (const int*)d_in[1];
    const int*   src = ei;
    const int*   dst = ei + EE;
    const float* W[4] = {(const float*)d_in[2], (const float*)d_in[4],
                         (const float*)d_in[6], (const float*)d_in[8]};
    const float* b[4] = {(const float*)d_in[3], (const float*)d_in[5],
                         (const float*)d_in[7], (const float*)d_in[9]};
    const float* Wm2 = (const float*)d_in[12];
    const float* bm2 = (const float*)d_in[13];

    float* out_h = (float*)d_out;                 // [NN, 128]
    float* out_S = out_h + (size_t)NN * HD;       // [NN, 10]

    float *xw, *h1, *h2, *dinv;
    int* deg;
    cudaGetSymbolAddress((void**)&xw,   g_xw);
    cudaGetSymbolAddress((void**)&h1,   g_h1);
    cudaGetSymbolAddress((void**)&h2,   g_h2);
    cudaGetSymbolAddress((void**)&dinv, g_dinv);
    cudaGetSymbolAddress((void**)&deg,  g_deg);

    // Degree, normalization, CSR build (once per launch)
    k_zero_deg<<<(NN + 255) / 256, 256>>>(deg);
    k_hist<<<(EE + 255) / 256, 256>>>(dst, deg);
    k_blockred<<<SCAN_BLOCKS, 256>>>(deg, dinv);
    k_scansums<<<1, 256>>>();
    k_scanfinal<<<SCAN_BLOCKS, 256>>>(deg);
    k_fill<<<(EE + 255) / 256, 256>>>(src, dst, dinv);

    const int gemm_blocks   = (NN + 127) / 128;           // 391
    const int gather_blocks = (NN * 32 + 255) / 256;      // 6250

    const float* in = x;
    float* houts[4] = {h1, h2, h1, out_h};
    for (int l = 0; l < 4; l++) {
        k_gemm<<<gemm_blocks, 256>>>(in, W[l], xw);
        k_gather<<<gather_blocks, 256>>>(xw, dinv, b[l], houts[l]);
        in = houts[l];
    }

    k_mlp<<<(NN + 7) / 8, 256>>>(out_h, Wm2, bm2, out_S);
}